// round 11
// baseline (speedup 1.0000x reference)
#include <cuda_runtime.h>
#include <cstdint>

// TaylorExp, 4 rows/warp, unrolled sweeps, row-hoisted q4 registers + fused
// p-pair LDS.64 (R8 structure) + WRITE-THROUGH output stores (st.global.wt):
// output bytes transit the LTS once (no dirty-line writeback pass) and never
// occupy L2, keeping the small x input resident across graph replays.
// Per row: p[0]=1, p[1+i]=2*s_quad*x[i]; q_ext[j]=x[j mod 16]/2 (j=0..18).
// out[m] = p[t>>4]*q[t&15], t=m-1 (m>=1); out[0]=1.

#define D 16
#define OPR 273
#define THREADS 256
#define ROWS_PER_BLOCK 32
#define RS 56

__device__ __forceinline__ void stwt4(float4* p, float4 v) {
#if __CUDA_ARCH__ >= 800
    __stwt(p, v);            // st.global.wt.v4 — write-through streaming store
#else
    *p = v;
#endif
}

__global__ __launch_bounds__(THREADS)
void taylor_hqw_kernel(const float* __restrict__ x,
                       float* __restrict__ out,
                       int rows)
{
    __shared__ __align__(16) float sm[(THREADS / 32) * 4 * RS]; // 1792 floats

    const int tid = threadIdx.x;
    const int row0 = blockIdx.x * ROWS_PER_BLOCK;

    if (row0 + ROWS_PER_BLOCK <= rows) {
        // ---- stage pp2/q for 32 rows (coalesced 512B x load) ----
        if (tid < 128) {
            const int lr = tid >> 2;                 // local row 0..31
            const int jb = (tid & 3) << 2;           // j base 0,4,8,12
            const float4 f = __ldg(reinterpret_cast<const float4*>(
                x + (size_t)(row0 + lr) * D + jb));
            const int rb = lr * RS;
            const int qb = rb + 34 + (((lr & 3) + 3) & 3);
            const float ps = 0.35355339059327378f;   // 2*s_quad
            const float v0 = f.x * ps, v1 = f.y * ps;
            const float v2 = f.z * ps, v3 = f.w * ps;
            sm[rb + 2 * (jb + 1)] = v0; sm[rb + 2 * (jb + 1) - 1] = v0;
            sm[rb + 2 * (jb + 2)] = v1; sm[rb + 2 * (jb + 2) - 1] = v1;
            sm[rb + 2 * (jb + 3)] = v2; sm[rb + 2 * (jb + 3) - 1] = v2;
            sm[rb + 2 * (jb + 4)] = v3; sm[rb + 2 * (jb + 4) - 1] = v3;
            sm[qb + jb + 0] = f.x * 0.5f;
            sm[qb + jb + 1] = f.y * 0.5f;
            sm[qb + jb + 2] = f.z * 0.5f;
            sm[qb + jb + 3] = f.w * 0.5f;
            if (jb == 0) {
                sm[rb] = 1.0f;                       // pp2[0].x = p[0]
                sm[qb + 16] = f.x * 0.5f;            // wrap replicas
                sm[qb + 17] = f.y * 0.5f;
                sm[qb + 18] = f.z * 0.5f;
            }
            if (jb == 12) sm[rb + 33] = v3;          // pp2[16].y pad
        }
        __syncthreads();

        const int warp = tid >> 5;
        const int lane = tid & 31;
        const int l4 = lane << 2;
        const int wb = warp * (4 * RS);

        const int rb0 = wb,        rb1 = wb + RS;
        const int rb2 = wb + 2*RS, rb3 = wb + 3*RS;
        const int qb0 = rb0 + 37, qb1 = rb1 + 34;
        const int qb2 = rb2 + 35, qb3 = rb3 + 36;

        // row-constant q4 vectors (hoisted; b0_rl = (4*(lane&3)+15-rl)&15)
        const int a3 = (lane & 3) << 2;
        const float4 q40 = *reinterpret_cast<const float4*>(&sm[qb0 + ((a3 + 15) & 15)]);
        const float4 q41 = *reinterpret_cast<const float4*>(&sm[qb1 + ((a3 + 14) & 15)]);
        const float4 q42 = *reinterpret_cast<const float4*>(&sm[qb2 + ((a3 + 13) & 15)]);
        const float4 q43 = *reinterpret_cast<const float4*>(&sm[qb3 + ((a3 + 12) & 15)]);

        float4* __restrict__ ob = reinterpret_cast<float4*>(
            out + (size_t)(row0 + warp * 4) * OPR) + lane;

#define BODY(RB, T0, T0A, Q4, V)                                            \
        {                                                                   \
            const int t0_ = (T0);                                           \
            const int b0_ = t0_ & 15;                                       \
            const int a0_ = (T0A) >> 4;                                     \
            const float2 pq_ =                                              \
                *reinterpret_cast<const float2*>(&sm[(RB) + 2 * a0_]);      \
            V.x = pq_.x * (Q4).x;                                           \
            V.y = (b0_ >= 15 ? pq_.y : pq_.x) * (Q4).y;                     \
            V.z = (b0_ >= 14 ? pq_.y : pq_.x) * (Q4).z;                     \
            V.w = (b0_ >= 13 ? pq_.y : pq_.x) * (Q4).w;                     \
        }
#define SEL4(C, A, B) make_float4((C)?(A).x:(B).x, (C)?(A).y:(B).y, \
                                  (C)?(A).z:(B).z, (C)?(A).w:(B).w)

        float4 v;

        // s=0: row0, C=-1; lane0 fixup from q40 registers.
        BODY(rb0, l4 - 1, (l4 - 1) < 0 ? 0 : (l4 - 1), q40, v);
        if (lane == 0) { v.x = 1.0f; v.y = q40.y; v.z = q40.z; v.w = q40.w; }
        stwt4(&ob[0], v);

        // s=1: row0, C=127.
        BODY(rb0, l4 + 127, l4 + 127, q40, v);
        stwt4(&ob[32], v);

        // s=2: lanes<=4 row0 (C=255), lanes>=5 row1 (C=-18); lane4 mixed.
        {
            const bool hi = lane >= 5;
            const int t0 = l4 + (hi ? -18 : 255);
            const float4 q4m = SEL4(hi, q41, q40);
            BODY(hi ? rb1 : rb0, t0, t0, q4m, v);
            if (lane == 4) { v.y = 1.0f; v.z = sm[qb1]; v.w = sm[qb1 + 1]; }
            stwt4(&ob[64], v);
        }

        // s=3: row1, C=110.
        BODY(rb1, l4 + 110, l4 + 110, q41, v);
        stwt4(&ob[96], v);

        // s=4: lanes<=8 row1 (C=238), lanes>=9 row2 (C=-35); lane8 mixed.
        {
            const bool hi = lane >= 9;
            const int t0 = l4 + (hi ? -35 : 238);
            const float4 q4m = SEL4(hi, q42, q41);
            BODY(hi ? rb2 : rb1, t0, t0, q4m, v);
            if (lane == 8) { v.z = 1.0f; v.w = q42.w; }   // q2[0] = q42.w (b0=13)
            stwt4(&ob[128], v);
        }

        // s=5: row2, C=93.
        BODY(rb2, l4 + 93, l4 + 93, q42, v);
        stwt4(&ob[160], v);

        // s=6: lanes<=12 row2 (C=221), lanes>=13 row3 (C=-52); lane12 mixed.
        {
            const bool hi = lane >= 13;
            const int t0 = l4 + (hi ? -52 : 221);
            const float4 q4m = SEL4(hi, q43, q42);
            BODY(hi ? rb3 : rb2, t0, t0, q4m, v);
            if (lane == 12) { v.w = 1.0f; }
            stwt4(&ob[192], v);
        }

        // s=7: row3, C=76.
        BODY(rb3, l4 + 76, l4 + 76, q43, v);
        stwt4(&ob[224], v);

        // s=8: row3, C=204, lanes 0..16 only.
        if (lane < 17) {
            BODY(rb3, l4 + 204, l4 + 204, q43, v);
            stwt4(&ob[256], v);
        }
#undef BODY
#undef SEL4
    } else {
        // partial tail block (not hit for the bench shape): scalar fallback
        const float s_quad = 0.17677669529663689f;
        const unsigned int iend = (unsigned int)rows * OPR;
        for (unsigned int g = (unsigned int)row0 * OPR + tid; g < iend;
             g += THREADS) {
            const unsigned int row = g / OPR;
            const int mm = (int)(g - row * OPR);
            const float* xr = x + (size_t)row * D;
            float vv;
            if (mm == 0) vv = 1.0f;
            else if (mm < 17) vv = xr[mm - 1] * 0.5f;
            else { const int k = mm - 17; vv = xr[k >> 4] * xr[k & 15] * s_quad; }
            out[g] = vv;
        }
    }
}

extern "C" void kernel_launch(void* const* d_in, const int* in_sizes, int n_in,
                              void* d_out, int out_size) {
    const float* x = (const float*)d_in[0];
    float* out = (float*)d_out;

    const int rows = in_sizes[0] / D;                            // 262144
    const int blocks = (rows + ROWS_PER_BLOCK - 1) / ROWS_PER_BLOCK; // 8192

    taylor_hqw_kernel<<<blocks, THREADS>>>(x, out, rows);
}

// round 13
// speedup vs baseline: 1.0999x; 1.0999x over previous
#include <cuda_runtime.h>
#include <cstdint>

// TaylorExp, 4 rows/warp, unrolled sweeps, row-hoisted q4 registers + fused
// p-pair LDS.64 + evict-first (cs) output stores + evict-last x loads.
// cs stores keep the 286MB output stream from thrashing L2; evict_last pins
// the 17MB x input in L2 across graph replays. ptxas on sm_103a only allows
// .L2::evict_last on 256-bit loads -> stage x with ld.global.nc.v8.b32
// (64 threads x 32B = half row each).
// Per row: p[0]=1, p[1+i]=2*s_quad*x[i]; q_ext[j]=x[j mod 16]/2 (j=0..18).
// out[m] = p[t>>4]*q[t&15], t=m-1 (m>=1); out[0]=1.

#define D 16
#define OPR 273
#define THREADS 256
#define ROWS_PER_BLOCK 32
#define RS 56

__device__ __forceinline__ void stcs4(float4* p, float4 v) {
#if __CUDA_ARCH__ >= 800
    __stcs(p, v);            // st.global.cs.v4 — evict-first streaming store
#else
    *p = v;
#endif
}

__device__ __forceinline__ void ldg_el8(const float* p, float r[8]) {
#if __CUDA_ARCH__ >= 1000
    asm volatile(
        "ld.global.nc.L2::evict_last.v8.b32 {%0,%1,%2,%3,%4,%5,%6,%7}, [%8];"
        : "=f"(r[0]), "=f"(r[1]), "=f"(r[2]), "=f"(r[3]),
          "=f"(r[4]), "=f"(r[5]), "=f"(r[6]), "=f"(r[7])
        : "l"(p));
#else
    const float4 a = *reinterpret_cast<const float4*>(p);
    const float4 b = *reinterpret_cast<const float4*>(p + 4);
    r[0] = a.x; r[1] = a.y; r[2] = a.z; r[3] = a.w;
    r[4] = b.x; r[5] = b.y; r[6] = b.z; r[7] = b.w;
#endif
}

__global__ __launch_bounds__(THREADS)
void taylor_hqs3_kernel(const float* __restrict__ x,
                        float* __restrict__ out,
                        int rows)
{
    __shared__ __align__(16) float sm[(THREADS / 32) * 4 * RS]; // 1792 floats

    const int tid = threadIdx.x;
    const int row0 = blockIdx.x * ROWS_PER_BLOCK;

    if (row0 + ROWS_PER_BLOCK <= rows) {
        // ---- stage pp2/q for 32 rows: 64 threads, 32B (half row) each ----
        if (tid < 64) {
            const int lr = tid >> 1;                 // local row 0..31
            const int jb = (tid & 1) << 3;           // j base 0 or 8
            float f[8];
            ldg_el8(x + (size_t)(row0 + lr) * D + jb, f);
            const int rb = lr * RS;
            const int qb = rb + 34 + (((lr & 3) + 3) & 3);
            const float ps = 0.35355339059327378f;   // 2*s_quad
            #pragma unroll
            for (int i = 0; i < 8; ++i) {
                const float pv = f[i] * ps;
                sm[rb + 2 * (jb + i + 1)]     = pv;  // pp2[jb+i+1].x = p
                sm[rb + 2 * (jb + i + 1) - 1] = pv;  // pp2[jb+i  ].y = p
                sm[qb + jb + i] = f[i] * 0.5f;       // q[jb+i]
            }
            if (jb == 0) {
                sm[rb] = 1.0f;                       // pp2[0].x = p[0]
                sm[qb + 16] = f[0] * 0.5f;           // wrap replicas q[16..18]
                sm[qb + 17] = f[1] * 0.5f;
                sm[qb + 18] = f[2] * 0.5f;
            } else {
                sm[rb + 33] = f[7] * ps;             // pp2[16].y pad
            }
        }
        __syncthreads();

        const int warp = tid >> 5;
        const int lane = tid & 31;
        const int l4 = lane << 2;
        const int wb = warp * (4 * RS);

        const int rb0 = wb,        rb1 = wb + RS;
        const int rb2 = wb + 2*RS, rb3 = wb + 3*RS;
        const int qb0 = rb0 + 37, qb1 = rb1 + 34;
        const int qb2 = rb2 + 35, qb3 = rb3 + 36;

        // row-constant q4 vectors (hoisted; b0_rl = (4*(lane&3)+15-rl)&15)
        const int a3 = (lane & 3) << 2;
        const float4 q40 = *reinterpret_cast<const float4*>(&sm[qb0 + ((a3 + 15) & 15)]);
        const float4 q41 = *reinterpret_cast<const float4*>(&sm[qb1 + ((a3 + 14) & 15)]);
        const float4 q42 = *reinterpret_cast<const float4*>(&sm[qb2 + ((a3 + 13) & 15)]);
        const float4 q43 = *reinterpret_cast<const float4*>(&sm[qb3 + ((a3 + 12) & 15)]);

        float4* __restrict__ ob = reinterpret_cast<float4*>(
            out + (size_t)(row0 + warp * 4) * OPR) + lane;

#define BODY(RB, T0, T0A, Q4, V)                                            \
        {                                                                   \
            const int t0_ = (T0);                                           \
            const int b0_ = t0_ & 15;                                       \
            const int a0_ = (T0A) >> 4;                                     \
            const float2 pq_ =                                              \
                *reinterpret_cast<const float2*>(&sm[(RB) + 2 * a0_]);      \
            V.x = pq_.x * (Q4).x;                                           \
            V.y = (b0_ >= 15 ? pq_.y : pq_.x) * (Q4).y;                     \
            V.z = (b0_ >= 14 ? pq_.y : pq_.x) * (Q4).z;                     \
            V.w = (b0_ >= 13 ? pq_.y : pq_.x) * (Q4).w;                     \
        }
#define SEL4(C, A, B) make_float4((C)?(A).x:(B).x, (C)?(A).y:(B).y, \
                                  (C)?(A).z:(B).z, (C)?(A).w:(B).w)

        float4 v;

        // s=0: row0, C=-1; lane0 fixup from q40 registers.
        BODY(rb0, l4 - 1, (l4 - 1) < 0 ? 0 : (l4 - 1), q40, v);
        if (lane == 0) { v.x = 1.0f; v.y = q40.y; v.z = q40.z; v.w = q40.w; }
        stcs4(&ob[0], v);

        // s=1: row0, C=127.
        BODY(rb0, l4 + 127, l4 + 127, q40, v);
        stcs4(&ob[32], v);

        // s=2: lanes<=4 row0 (C=255), lanes>=5 row1 (C=-18); lane4 mixed.
        {
            const bool hi = lane >= 5;
            const int t0 = l4 + (hi ? -18 : 255);
            const float4 q4m = SEL4(hi, q41, q40);
            BODY(hi ? rb1 : rb0, t0, t0, q4m, v);
            if (lane == 4) { v.y = 1.0f; v.z = sm[qb1]; v.w = sm[qb1 + 1]; }
            stcs4(&ob[64], v);
        }

        // s=3: row1, C=110.
        BODY(rb1, l4 + 110, l4 + 110, q41, v);
        stcs4(&ob[96], v);

        // s=4: lanes<=8 row1 (C=238), lanes>=9 row2 (C=-35); lane8 mixed.
        {
            const bool hi = lane >= 9;
            const int t0 = l4 + (hi ? -35 : 238);
            const float4 q4m = SEL4(hi, q42, q41);
            BODY(hi ? rb2 : rb1, t0, t0, q4m, v);
            if (lane == 8) { v.z = 1.0f; v.w = q42.w; }   // q2[0] = q42.w (b0=13)
            stcs4(&ob[128], v);
        }

        // s=5: row2, C=93.
        BODY(rb2, l4 + 93, l4 + 93, q42, v);
        stcs4(&ob[160], v);

        // s=6: lanes<=12 row2 (C=221), lanes>=13 row3 (C=-52); lane12 mixed.
        {
            const bool hi = lane >= 13;
            const int t0 = l4 + (hi ? -52 : 221);
            const float4 q4m = SEL4(hi, q43, q42);
            BODY(hi ? rb3 : rb2, t0, t0, q4m, v);
            if (lane == 12) { v.w = 1.0f; }
            stcs4(&ob[192], v);
        }

        // s=7: row3, C=76.
        BODY(rb3, l4 + 76, l4 + 76, q43, v);
        stcs4(&ob[224], v);

        // s=8: row3, C=204, lanes 0..16 only.
        if (lane < 17) {
            BODY(rb3, l4 + 204, l4 + 204, q43, v);
            stcs4(&ob[256], v);
        }
#undef BODY
#undef SEL4
    } else {
        // partial tail block (not hit for the bench shape): scalar fallback
        const float s_quad = 0.17677669529663689f;
        const unsigned int iend = (unsigned int)rows * OPR;
        for (unsigned int g = (unsigned int)row0 * OPR + tid; g < iend;
             g += THREADS) {
            const unsigned int row = g / OPR;
            const int mm = (int)(g - row * OPR);
            const float* xr = x + (size_t)row * D;
            float vv;
            if (mm == 0) vv = 1.0f;
            else if (mm < 17) vv = xr[mm - 1] * 0.5f;
            else { const int k = mm - 17; vv = xr[k >> 4] * xr[k & 15] * s_quad; }
            out[g] = vv;
        }
    }
}

extern "C" void kernel_launch(void* const* d_in, const int* in_sizes, int n_in,
                              void* d_out, int out_size) {
    const float* x = (const float*)d_in[0];
    float* out = (float*)d_out;

    const int rows = in_sizes[0] / D;                            // 262144
    const int blocks = (rows + ROWS_PER_BLOCK - 1) / ROWS_PER_BLOCK; // 8192

    taylor_hqs3_kernel<<<blocks, THREADS>>>(x, out, rows);
}

// round 14
// speedup vs baseline: 1.1015x; 1.0014x over previous
#include <cuda_runtime.h>
#include <cstdint>

// TaylorExp, 4 rows/warp, unrolled sweeps, row-hoisted q4 registers + fused
// p-pair LDS.64 (R8 structure) + streaming (evict-first) output stores.
// Per row: p[0]=1, p[1+i]=2*s_quad*x[i]; q_ext[j]=x[j mod 16]/2 (j=0..18).
// out[m] = p[t>>4]*q[t&15], t=m-1 (m>=1); out[0]=1.
// R14 = R10 resubmitted verbatim (reproducibility check on the best kernel).

#define D 16
#define OPR 273
#define THREADS 256
#define ROWS_PER_BLOCK 32
#define RS 56

__device__ __forceinline__ void stcs4(float4* p, float4 v) {
#if __CUDA_ARCH__ >= 800
    __stcs(p, v);            // st.global.cs.v4 — evict-first streaming store
#else
    *p = v;
#endif
}

__global__ __launch_bounds__(THREADS)
void taylor_hqs_kernel(const float* __restrict__ x,
                       float* __restrict__ out,
                       int rows)
{
    __shared__ __align__(16) float sm[(THREADS / 32) * 4 * RS]; // 1792 floats

    const int tid = threadIdx.x;
    const int row0 = blockIdx.x * ROWS_PER_BLOCK;

    if (row0 + ROWS_PER_BLOCK <= rows) {
        // ---- stage pp2/q for 32 rows (coalesced 512B x load) ----
        if (tid < 128) {
            const int lr = tid >> 2;                 // local row 0..31
            const int jb = (tid & 3) << 2;           // j base 0,4,8,12
            const float4 f = __ldg(reinterpret_cast<const float4*>(
                x + (size_t)(row0 + lr) * D + jb));
            const int rb = lr * RS;
            const int qb = rb + 34 + (((lr & 3) + 3) & 3);
            const float ps = 0.35355339059327378f;   // 2*s_quad
            const float v0 = f.x * ps, v1 = f.y * ps;
            const float v2 = f.z * ps, v3 = f.w * ps;
            sm[rb + 2 * (jb + 1)] = v0; sm[rb + 2 * (jb + 1) - 1] = v0;
            sm[rb + 2 * (jb + 2)] = v1; sm[rb + 2 * (jb + 2) - 1] = v1;
            sm[rb + 2 * (jb + 3)] = v2; sm[rb + 2 * (jb + 3) - 1] = v2;
            sm[rb + 2 * (jb + 4)] = v3; sm[rb + 2 * (jb + 4) - 1] = v3;
            sm[qb + jb + 0] = f.x * 0.5f;
            sm[qb + jb + 1] = f.y * 0.5f;
            sm[qb + jb + 2] = f.z * 0.5f;
            sm[qb + jb + 3] = f.w * 0.5f;
            if (jb == 0) {
                sm[rb] = 1.0f;                       // pp2[0].x = p[0]
                sm[qb + 16] = f.x * 0.5f;            // wrap replicas
                sm[qb + 17] = f.y * 0.5f;
                sm[qb + 18] = f.z * 0.5f;
            }
            if (jb == 12) sm[rb + 33] = v3;          // pp2[16].y pad
        }
        __syncthreads();

        const int warp = tid >> 5;
        const int lane = tid & 31;
        const int l4 = lane << 2;
        const int wb = warp * (4 * RS);

        const int rb0 = wb,        rb1 = wb + RS;
        const int rb2 = wb + 2*RS, rb3 = wb + 3*RS;
        const int qb0 = rb0 + 37, qb1 = rb1 + 34;
        const int qb2 = rb2 + 35, qb3 = rb3 + 36;

        // row-constant q4 vectors (hoisted; b0_rl = (4*(lane&3)+15-rl)&15)
        const int a3 = (lane & 3) << 2;
        const float4 q40 = *reinterpret_cast<const float4*>(&sm[qb0 + ((a3 + 15) & 15)]);
        const float4 q41 = *reinterpret_cast<const float4*>(&sm[qb1 + ((a3 + 14) & 15)]);
        const float4 q42 = *reinterpret_cast<const float4*>(&sm[qb2 + ((a3 + 13) & 15)]);
        const float4 q43 = *reinterpret_cast<const float4*>(&sm[qb3 + ((a3 + 12) & 15)]);

        float4* __restrict__ ob = reinterpret_cast<float4*>(
            out + (size_t)(row0 + warp * 4) * OPR) + lane;

#define BODY(RB, T0, T0A, Q4, V)                                            \
        {                                                                   \
            const int t0_ = (T0);                                           \
            const int b0_ = t0_ & 15;                                       \
            const int a0_ = (T0A) >> 4;                                     \
            const float2 pq_ =                                              \
                *reinterpret_cast<const float2*>(&sm[(RB) + 2 * a0_]);      \
            V.x = pq_.x * (Q4).x;                                           \
            V.y = (b0_ >= 15 ? pq_.y : pq_.x) * (Q4).y;                     \
            V.z = (b0_ >= 14 ? pq_.y : pq_.x) * (Q4).z;                     \
            V.w = (b0_ >= 13 ? pq_.y : pq_.x) * (Q4).w;                     \
        }
#define SEL4(C, A, B) make_float4((C)?(A).x:(B).x, (C)?(A).y:(B).y, \
                                  (C)?(A).z:(B).z, (C)?(A).w:(B).w)

        float4 v;

        // s=0: row0, C=-1; lane0 fixup from q40 registers.
        BODY(rb0, l4 - 1, (l4 - 1) < 0 ? 0 : (l4 - 1), q40, v);
        if (lane == 0) { v.x = 1.0f; v.y = q40.y; v.z = q40.z; v.w = q40.w; }
        stcs4(&ob[0], v);

        // s=1: row0, C=127.
        BODY(rb0, l4 + 127, l4 + 127, q40, v);
        stcs4(&ob[32], v);

        // s=2: lanes<=4 row0 (C=255), lanes>=5 row1 (C=-18); lane4 mixed.
        {
            const bool hi = lane >= 5;
            const int t0 = l4 + (hi ? -18 : 255);
            const float4 q4m = SEL4(hi, q41, q40);
            BODY(hi ? rb1 : rb0, t0, t0, q4m, v);
            if (lane == 4) { v.y = 1.0f; v.z = sm[qb1]; v.w = sm[qb1 + 1]; }
            stcs4(&ob[64], v);
        }

        // s=3: row1, C=110.
        BODY(rb1, l4 + 110, l4 + 110, q41, v);
        stcs4(&ob[96], v);

        // s=4: lanes<=8 row1 (C=238), lanes>=9 row2 (C=-35); lane8 mixed.
        {
            const bool hi = lane >= 9;
            const int t0 = l4 + (hi ? -35 : 238);
            const float4 q4m = SEL4(hi, q42, q41);
            BODY(hi ? rb2 : rb1, t0, t0, q4m, v);
            if (lane == 8) { v.z = 1.0f; v.w = q42.w; }   // q2[0] = q42.w (b0=13)
            stcs4(&ob[128], v);
        }

        // s=5: row2, C=93.
        BODY(rb2, l4 + 93, l4 + 93, q42, v);
        stcs4(&ob[160], v);

        // s=6: lanes<=12 row2 (C=221), lanes>=13 row3 (C=-52); lane12 mixed.
        {
            const bool hi = lane >= 13;
            const int t0 = l4 + (hi ? -52 : 221);
            const float4 q4m = SEL4(hi, q43, q42);
            BODY(hi ? rb3 : rb2, t0, t0, q4m, v);
            if (lane == 12) { v.w = 1.0f; }
            stcs4(&ob[192], v);
        }

        // s=7: row3, C=76.
        BODY(rb3, l4 + 76, l4 + 76, q43, v);
        stcs4(&ob[224], v);

        // s=8: row3, C=204, lanes 0..16 only.
        if (lane < 17) {
            BODY(rb3, l4 + 204, l4 + 204, q43, v);
            stcs4(&ob[256], v);
        }
#undef BODY
#undef SEL4
    } else {
        // partial tail block (not hit for the bench shape): scalar fallback
        const float s_quad = 0.17677669529663689f;
        const unsigned int iend = (unsigned int)rows * OPR;
        for (unsigned int g = (unsigned int)row0 * OPR + tid; g < iend;
             g += THREADS) {
            const unsigned int row = g / OPR;
            const int mm = (int)(g - row * OPR);
            const float* xr = x + (size_t)row * D;
            float vv;
            if (mm == 0) vv = 1.0f;
            else if (mm < 17) vv = xr[mm - 1] * 0.5f;
            else { const int k = mm - 17; vv = xr[k >> 4] * xr[k & 15] * s_quad; }
            out[g] = vv;
        }
    }
}

extern "C" void kernel_launch(void* const* d_in, const int* in_sizes, int n_in,
                              void* d_out, int out_size) {
    const float* x = (const float*)d_in[0];
    float* out = (float*)d_out;

    const int rows = in_sizes[0] / D;                            // 262144
    const int blocks = (rows + ROWS_PER_BLOCK - 1) / ROWS_PER_BLOCK; // 8192

    taylor_hqs_kernel<<<blocks, THREADS>>>(x, out, rows);
}

// round 15
// speedup vs baseline: 1.1094x; 1.0071x over previous
#include <cuda_runtime.h>
#include <cstdint>

// TaylorExp — FINAL kernel (converged, R10 structure).
// out[row] = [1, x/sqrt(sqrt(16)), vec(x⊗x)/(sqrt(2)*sqrt(16))], d=16 → 273/row.
//
// Structure: 4 rows per warp; per-block smem staging of per-row factor arrays
//   p[0]=1, p[1+i]=2*s_quad*x[i] (stored as overlapping pairs pp2 for one
//   LDS.64 per sweep), q_ext[j]=x[j mod 16]/2 (3 wrap replicas);
// out[m] = p[(m-1)>>4] * q[(m-1)&15] for m>=1, out[0]=1 — one unified
// product formula covering constant/linear/quadratic regions.
// 9 fully-unrolled 32-lane sweeps per warp group; all row crossings are at
// compile-time (sweep,lane) positions with tiny register fixups; each lane's
// q4 vector is ROW-CONSTANT and hoisted into registers (per-row smem padding
// keeps every LDS.128 16B-aligned); all output stores are 16B-aligned
// st.global.cs.v4 (evict-first) — the policy that keeps the 286MB output
// stream from thrashing L2 across graph replays (worth ~5us wall vs wb;
// wt and L2::evict_last both measured worse).

#define D 16
#define OPR 273
#define THREADS 256
#define ROWS_PER_BLOCK 32
#define RS 56

__device__ __forceinline__ void stcs4(float4* p, float4 v) {
#if __CUDA_ARCH__ >= 800
    __stcs(p, v);            // st.global.cs.v4 — evict-first streaming store
#else
    *p = v;
#endif
}

__global__ __launch_bounds__(THREADS)
void taylor_hqs_kernel(const float* __restrict__ x,
                       float* __restrict__ out,
                       int rows)
{
    __shared__ __align__(16) float sm[(THREADS / 32) * 4 * RS]; // 1792 floats

    const int tid = threadIdx.x;
    const int row0 = blockIdx.x * ROWS_PER_BLOCK;

    if (row0 + ROWS_PER_BLOCK <= rows) {
        // ---- stage pp2/q for 32 rows (coalesced 512B x load) ----
        if (tid < 128) {
            const int lr = tid >> 2;                 // local row 0..31
            const int jb = (tid & 3) << 2;           // j base 0,4,8,12
            const float4 f = __ldg(reinterpret_cast<const float4*>(
                x + (size_t)(row0 + lr) * D + jb));
            const int rb = lr * RS;
            const int qb = rb + 34 + (((lr & 3) + 3) & 3);
            const float ps = 0.35355339059327378f;   // 2*s_quad
            const float v0 = f.x * ps, v1 = f.y * ps;
            const float v2 = f.z * ps, v3 = f.w * ps;
            sm[rb + 2 * (jb + 1)] = v0; sm[rb + 2 * (jb + 1) - 1] = v0;
            sm[rb + 2 * (jb + 2)] = v1; sm[rb + 2 * (jb + 2) - 1] = v1;
            sm[rb + 2 * (jb + 3)] = v2; sm[rb + 2 * (jb + 3) - 1] = v2;
            sm[rb + 2 * (jb + 4)] = v3; sm[rb + 2 * (jb + 4) - 1] = v3;
            sm[qb + jb + 0] = f.x * 0.5f;
            sm[qb + jb + 1] = f.y * 0.5f;
            sm[qb + jb + 2] = f.z * 0.5f;
            sm[qb + jb + 3] = f.w * 0.5f;
            if (jb == 0) {
                sm[rb] = 1.0f;                       // pp2[0].x = p[0]
                sm[qb + 16] = f.x * 0.5f;            // wrap replicas
                sm[qb + 17] = f.y * 0.5f;
                sm[qb + 18] = f.z * 0.5f;
            }
            if (jb == 12) sm[rb + 33] = v3;          // pp2[16].y pad
        }
        __syncthreads();

        const int warp = tid >> 5;
        const int lane = tid & 31;
        const int l4 = lane << 2;
        const int wb = warp * (4 * RS);

        const int rb0 = wb,        rb1 = wb + RS;
        const int rb2 = wb + 2*RS, rb3 = wb + 3*RS;
        const int qb0 = rb0 + 37, qb1 = rb1 + 34;
        const int qb2 = rb2 + 35, qb3 = rb3 + 36;

        // row-constant q4 vectors (hoisted; b0_rl = (4*(lane&3)+15-rl)&15)
        const int a3 = (lane & 3) << 2;
        const float4 q40 = *reinterpret_cast<const float4*>(&sm[qb0 + ((a3 + 15) & 15)]);
        const float4 q41 = *reinterpret_cast<const float4*>(&sm[qb1 + ((a3 + 14) & 15)]);
        const float4 q42 = *reinterpret_cast<const float4*>(&sm[qb2 + ((a3 + 13) & 15)]);
        const float4 q43 = *reinterpret_cast<const float4*>(&sm[qb3 + ((a3 + 12) & 15)]);

        float4* __restrict__ ob = reinterpret_cast<float4*>(
            out + (size_t)(row0 + warp * 4) * OPR) + lane;

#define BODY(RB, T0, T0A, Q4, V)                                            \
        {                                                                   \
            const int t0_ = (T0);                                           \
            const int b0_ = t0_ & 15;                                       \
            const int a0_ = (T0A) >> 4;                                     \
            const float2 pq_ =                                              \
                *reinterpret_cast<const float2*>(&sm[(RB) + 2 * a0_]);      \
            V.x = pq_.x * (Q4).x;                                           \
            V.y = (b0_ >= 15 ? pq_.y : pq_.x) * (Q4).y;                     \
            V.z = (b0_ >= 14 ? pq_.y : pq_.x) * (Q4).z;                     \
            V.w = (b0_ >= 13 ? pq_.y : pq_.x) * (Q4).w;                     \
        }
#define SEL4(C, A, B) make_float4((C)?(A).x:(B).x, (C)?(A).y:(B).y, \
                                  (C)?(A).z:(B).z, (C)?(A).w:(B).w)

        float4 v;

        // s=0: row0, C=-1; lane0 fixup from q40 registers.
        BODY(rb0, l4 - 1, (l4 - 1) < 0 ? 0 : (l4 - 1), q40, v);
        if (lane == 0) { v.x = 1.0f; v.y = q40.y; v.z = q40.z; v.w = q40.w; }
        stcs4(&ob[0], v);

        // s=1: row0, C=127.
        BODY(rb0, l4 + 127, l4 + 127, q40, v);
        stcs4(&ob[32], v);

        // s=2: lanes<=4 row0 (C=255), lanes>=5 row1 (C=-18); lane4 mixed.
        {
            const bool hi = lane >= 5;
            const int t0 = l4 + (hi ? -18 : 255);
            const float4 q4m = SEL4(hi, q41, q40);
            BODY(hi ? rb1 : rb0, t0, t0, q4m, v);
            if (lane == 4) { v.y = 1.0f; v.z = sm[qb1]; v.w = sm[qb1 + 1]; }
            stcs4(&ob[64], v);
        }

        // s=3: row1, C=110.
        BODY(rb1, l4 + 110, l4 + 110, q41, v);
        stcs4(&ob[96], v);

        // s=4: lanes<=8 row1 (C=238), lanes>=9 row2 (C=-35); lane8 mixed.
        {
            const bool hi = lane >= 9;
            const int t0 = l4 + (hi ? -35 : 238);
            const float4 q4m = SEL4(hi, q42, q41);
            BODY(hi ? rb2 : rb1, t0, t0, q4m, v);
            if (lane == 8) { v.z = 1.0f; v.w = q42.w; }   // q2[0] = q42.w (b0=13)
            stcs4(&ob[128], v);
        }

        // s=5: row2, C=93.
        BODY(rb2, l4 + 93, l4 + 93, q42, v);
        stcs4(&ob[160], v);

        // s=6: lanes<=12 row2 (C=221), lanes>=13 row3 (C=-52); lane12 mixed.
        {
            const bool hi = lane >= 13;
            const int t0 = l4 + (hi ? -52 : 221);
            const float4 q4m = SEL4(hi, q43, q42);
            BODY(hi ? rb3 : rb2, t0, t0, q4m, v);
            if (lane == 12) { v.w = 1.0f; }
            stcs4(&ob[192], v);
        }

        // s=7: row3, C=76.
        BODY(rb3, l4 + 76, l4 + 76, q43, v);
        stcs4(&ob[224], v);

        // s=8: row3, C=204, lanes 0..16 only.
        if (lane < 17) {
            BODY(rb3, l4 + 204, l4 + 204, q43, v);
            stcs4(&ob[256], v);
        }
#undef BODY
#undef SEL4
    } else {
        // partial tail block (not hit for the bench shape): scalar fallback
        const float s_quad = 0.17677669529663689f;
        const unsigned int iend = (unsigned int)rows * OPR;
        for (unsigned int g = (unsigned int)row0 * OPR + tid; g < iend;
             g += THREADS) {
            const unsigned int row = g / OPR;
            const int mm = (int)(g - row * OPR);
            const float* xr = x + (size_t)row * D;
            float vv;
            if (mm == 0) vv = 1.0f;
            else if (mm < 17) vv = xr[mm - 1] * 0.5f;
            else { const int k = mm - 17; vv = xr[k >> 4] * xr[k & 15] * s_quad; }
            out[g] = vv;
        }
    }
}

extern "C" void kernel_launch(void* const* d_in, const int* in_sizes, int n_in,
                              void* d_out, int out_size) {
    const float* x = (const float*)d_in[0];
    float* out = (float*)d_out;

    const int rows = in_sizes[0] / D;                            // 262144
    const int blocks = (rows + ROWS_PER_BLOCK - 1) / ROWS_PER_BLOCK; // 8192

    taylor_hqs_kernel<<<blocks, THREADS>>>(x, out, rows);
}